// round 9
// baseline (speedup 1.0000x reference)
#include <cuda_runtime.h>
#include <cuda_fp16.h>
#include <cstdint>
#include <math.h>

#define NN 8192
#define DD 128
#define BM 128
#define BN 64
#define BK 32
#define STR 40            // 80 B row stride: 16B-aligned, 5*row%8 -> conflict-free ldmatrix
#define RTILES 64         // row tiles of 128
#define CTILES 128        // col tiles of 64
#define NACT 4160         // sum_{r}(128-2r) upper-triangle tiles
#define NPAD 4352         // 17*256 zero-padded partials

__device__ __half X16[NN * DD];
__device__ float  g_partial[NPAD];
__device__ int    g_count;

__device__ __forceinline__ uint32_t smem_u32(const void* p) {
    uint32_t a;
    asm("{ .reg .u64 t; cvta.to.shared.u64 t, %1; cvt.u32.u64 %0, t; }" : "=r"(a) : "l"(p));
    return a;
}
__device__ __forceinline__ void cp_async16(uint32_t s, const void* g) {
    asm volatile("cp.async.cg.shared.global [%0], [%1], 16;" :: "r"(s), "l"(g) : "memory");
}
#define CP_COMMIT() asm volatile("cp.async.commit_group;" ::: "memory")
#define CP_WAIT(n)  asm volatile("cp.async.wait_group %0;" :: "n"(n) : "memory")

__device__ __forceinline__ void ldsm_x4(uint32_t& r0, uint32_t& r1, uint32_t& r2, uint32_t& r3,
                                        uint32_t addr) {
    asm volatile("ldmatrix.sync.aligned.m8n8.x4.shared.b16 {%0,%1,%2,%3}, [%4];"
                 : "=r"(r0), "=r"(r1), "=r"(r2), "=r"(r3) : "r"(addr));
}
__device__ __forceinline__ void mma16816(float* c, uint32_t a0, uint32_t a1, uint32_t a2,
                                         uint32_t a3, uint32_t b0, uint32_t b1) {
    asm volatile("mma.sync.aligned.m16n8k16.row.col.f32.f16.f16.f32 "
                 "{%0,%1,%2,%3}, {%4,%5,%6,%7}, {%8,%9}, {%0,%1,%2,%3};"
                 : "+f"(c[0]), "+f"(c[1]), "+f"(c[2]), "+f"(c[3])
                 : "r"(a0), "r"(a1), "r"(a2), "r"(a3), "r"(b0), "r"(b1));
}

__global__ void convert_kernel(const float* __restrict__ X) {
    int idx = (blockIdx.x * blockDim.x + threadIdx.x) * 4;
    float4 v = *(const float4*)&X[idx];
    __half2* o = (__half2*)&X16[idx];
    o[0] = __floats2half2_rn(v.x, v.y);
    o[1] = __floats2half2_rn(v.z, v.w);
}

// first linear index of row-tile r: tiles per row = 128-2r
__device__ __forceinline__ int tri_off(int r) { return r * (129 - r); }

__global__ __launch_bounds__(256, 3)
void sim_loss_mma(const float* __restrict__ margin,
                  const int* __restrict__ tgt,
                  float* __restrict__ out) {
    const int b = blockIdx.x;
    int by = (int)((129.0 - sqrt(16641.0 - 4.0 * (double)b)) * 0.5);
    while (tri_off(by + 1) <= b) ++by;
    while (tri_off(by) > b) --by;
    const int cx = 2 * by + (b - tri_off(by));    // col tile index (64-wide)
    const int rowBase = by * BM;
    const int colBase = cx * BN;
    const bool dtile = (colBase >> 7) == by;      // straddles the diagonal

    __shared__ __half As[2][BM * STR];
    __shared__ __half Bs[2][BN * STR];
    __shared__ int   cs[BN];
    __shared__ float cm[BN];
    __shared__ int   rt[BM];
    __shared__ float rm[BM];
    __shared__ float red[8];
    __shared__ int   flag;

    const int tid  = threadIdx.x;
    const int lane = tid & 31;
    const int wid  = tid >> 5;
    const int wm   = wid & 3;     // 4 m-blocks of 32
    const int wn   = wid >> 2;    // 2 n-blocks of 32

    const uint32_t sAb[2] = { smem_u32(As[0]), smem_u32(As[1]) };
    const uint32_t sBb[2] = { smem_u32(Bs[0]), smem_u32(Bs[1]) };

    // 768 x 16B per chunk (A:512, B:256) / 256 thr = 3 each
    auto prefetch = [&](int kc, int buf) {
#pragma unroll
        for (int p = 0; p < 3; p++) {
            int id = tid + p * 256;
            int isB  = id >> 9;
            int e    = id & 511;          // A: 0..511 ; B uses e<256
            int row  = e >> 2;
            int ch   = e & 3;
            const __half* src = &X16[(size_t)((isB ? colBase : rowBase) + row) * DD + kc * BK + ch * 8];
            uint32_t dst = (isB ? sBb[buf] : sAb[buf]) + (uint32_t)(row * STR + ch * 8) * 2;
            if (!isB || row < BN) cp_async16(dst, src);
        }
        CP_COMMIT();
    };

    float acc[2][4][4];
#pragma unroll
    for (int mi = 0; mi < 2; mi++)
#pragma unroll
        for (int ni = 0; ni < 4; ni++)
#pragma unroll
            for (int q = 0; q < 4; q++) acc[mi][ni][q] = 0.0f;

    prefetch(0, 0);

    if (tid < BM) {
        rt[tid] = tgt[rowBase + tid];
        rm[tid] = margin[rowBase + tid];
    }
    if (tid < BN) {
        cs[tid] = tgt[colBase + tid];
        cm[tid] = margin[colBase + tid];
    }

    const int lrow = lane & 15;
    const int lchk = lane >> 4;

#pragma unroll
    for (int kc = 0; kc < DD / BK; kc++) {
        const int buf = kc & 1;
        if (kc + 1 < DD / BK) {
            prefetch(kc + 1, buf ^ 1);
            CP_WAIT(1);
        } else {
            CP_WAIT(0);
        }
        __syncthreads();

#pragma unroll
        for (int ks = 0; ks < BK / 16; ks++) {
            uint32_t a[2][4];
#pragma unroll
            for (int mi = 0; mi < 2; mi++) {
                uint32_t addr = sAb[buf] + (uint32_t)((wm * 32 + mi * 16 + lrow) * STR + ks * 16 + lchk * 8) * 2;
                ldsm_x4(a[mi][0], a[mi][1], a[mi][2], a[mi][3], addr);
            }
            uint32_t bfr[2][4];
#pragma unroll
            for (int nb = 0; nb < 2; nb++) {
                uint32_t addr = sBb[buf] + (uint32_t)((wn * 32 + nb * 16 + lrow) * STR + ks * 16 + lchk * 8) * 2;
                ldsm_x4(bfr[nb][0], bfr[nb][1], bfr[nb][2], bfr[nb][3], addr);
            }
#pragma unroll
            for (int mi = 0; mi < 2; mi++)
#pragma unroll
                for (int ni = 0; ni < 4; ni++)
                    mma16816(acc[mi][ni], a[mi][0], a[mi][1], a[mi][2], a[mi][3],
                             bfr[ni >> 1][ni & 1], bfr[ni >> 1][2 + (ni & 1)]);
        }
        __syncthreads();
    }

    // ---- epilogue ----
    // frag: c0:(r,c) c1:(r,c+1) c2:(r+8,c) c3:(r+8,c+1); r=lane/4, c=2*(lane&3)
    const int r0l = (lane >> 2);
    const int c0l = (lane & 3) * 2;
    float local = 0.0f;

#pragma unroll
    for (int mi = 0; mi < 2; mi++) {
        const int rA = wm * 32 + mi * 16 + r0l;
        const int rB = rA + 8;
        const int   trA = rt[rA], trB = rt[rB];
        const float mgA = rm[rA], mgB = rm[rB];
#pragma unroll
        for (int ni = 0; ni < 4; ni++) {
            const int c0 = wn * 32 + ni * 8 + c0l;
            const int   tc0 = cs[c0], tc1 = cs[c0 + 1];
            const float mc0 = cm[c0], mc1 = cm[c0 + 1];
            float s, pos, neg;
            if (!dtile) {
                s = acc[mi][ni][0];
                pos = 2.0f * fmaxf(1.0f - s, 0.0f);
                neg = ((s > mgA) ? s : 0.0f) + ((s > mc0) ? s : 0.0f);
                local += (trA == tc0) ? pos : neg;
                s = acc[mi][ni][1];
                pos = 2.0f * fmaxf(1.0f - s, 0.0f);
                neg = ((s > mgA) ? s : 0.0f) + ((s > mc1) ? s : 0.0f);
                local += (trA == tc1) ? pos : neg;
                s = acc[mi][ni][2];
                pos = 2.0f * fmaxf(1.0f - s, 0.0f);
                neg = ((s > mgB) ? s : 0.0f) + ((s > mc0) ? s : 0.0f);
                local += (trB == tc0) ? pos : neg;
                s = acc[mi][ni][3];
                pos = 2.0f * fmaxf(1.0f - s, 0.0f);
                neg = ((s > mgB) ? s : 0.0f) + ((s > mc1) ? s : 0.0f);
                local += (trB == tc1) ? pos : neg;
            } else {
                // diagonal-straddling tile: resolve per element
                const int gi0 = rowBase + rA, gi1 = rowBase + rB;
                const int gj0 = colBase + c0, gj1 = colBase + c0 + 1;
#pragma unroll
                for (int q = 0; q < 4; q++) {
                    const int   gi = (q < 2) ? gi0 : gi1;
                    const int   gj = (q & 1) ? gj1 : gj0;
                    const int   tr = (q < 2) ? trA : trB;
                    const float mg = (q < 2) ? mgA : mgB;
                    const int   tc = (q & 1) ? tc1 : tc0;
                    const float mc = (q & 1) ? mc1 : mc0;
                    s = acc[mi][ni][q];
                    if (gi < gj) {
                        pos = 2.0f * fmaxf(1.0f - s, 0.0f);
                        neg = ((s > mg) ? s : 0.0f) + ((s > mc) ? s : 0.0f);
                        local += (tr == tc) ? pos : neg;
                    } else if (gi == gj) {
                        local += fmaxf(1.0f - s, 0.0f);   // self: same-class, s≈1
                    }
                }
            }
        }
    }

    // ---- block reduce ----
#pragma unroll
    for (int off = 16; off > 0; off >>= 1)
        local += __shfl_xor_sync(0xFFFFFFFFu, local, off);
    if (lane == 0) red[wid] = local;
    __syncthreads();

    if (tid == 0) {
        float s = 0.0f;
#pragma unroll
        for (int w = 0; w < 8; w++) s += red[w];
        g_partial[b] = s;
    }

    // ---- deterministic last-block final reduce ----
    __threadfence();
    __syncthreads();
    if (tid == 0) flag = (atomicAdd(&g_count, 1) == NACT - 1) ? 1 : 0;
    __syncthreads();
    if (flag) {
        float v = 0.0f;
#pragma unroll
        for (int p = 0; p < NPAD / 256; p++)
            v += g_partial[tid + p * 256];
#pragma unroll
        for (int off = 16; off > 0; off >>= 1)
            v += __shfl_xor_sync(0xFFFFFFFFu, v, off);
        if (lane == 0) red[wid] = v;
        __syncthreads();
        if (tid == 0) {
            float s = 0.0f;
#pragma unroll
            for (int w = 0; w < 8; w++) s += red[w];
            out[0] = s / (float)NN;
            g_count = 0;
        }
    }
}

extern "C" void kernel_launch(void* const* d_in, const int* in_sizes, int n_in,
                              void* d_out, int out_size) {
    const float* X      = (const float*)d_in[0];
    const float* margin = (const float*)d_in[1];
    const int*   tgt    = (const int*)d_in[2];
    float*       out    = (float*)d_out;

    convert_kernel<<<NN * DD / 4 / 256, 256>>>(X);
    sim_loss_mma<<<NACT, 256>>>(margin, tgt, out);
}

// round 10
// speedup vs baseline: 1.0334x; 1.0334x over previous
#include <cuda_runtime.h>
#include <cuda_fp16.h>
#include <cstdint>
#include <math.h>

#define NN 8192
#define DD 128
#define BM 128
#define BN 128
#define STR 136           // halves; row = 272 B = 17*16B (odd) -> conflict-free ldmatrix, 16B-aligned
#define TILES 64
#define NACT (TILES*(TILES+1)/2)   // 2080
#define NPAD 2304

__device__ __half X16[NN * DD];
__device__ float  g_partial[NPAD];
__device__ int    g_count;

__device__ __forceinline__ uint32_t smem_u32(const void* p) {
    uint32_t a;
    asm("{ .reg .u64 t; cvta.to.shared.u64 t, %1; cvt.u32.u64 %0, t; }" : "=r"(a) : "l"(p));
    return a;
}
__device__ __forceinline__ void cp_async16(uint32_t s, const void* g) {
    asm volatile("cp.async.cg.shared.global [%0], [%1], 16;" :: "r"(s), "l"(g) : "memory");
}
#define CP_COMMIT() asm volatile("cp.async.commit_group;" ::: "memory")
#define CP_WAIT0()  asm volatile("cp.async.wait_group 0;" ::: "memory")

__device__ __forceinline__ void ldsm_x4(uint32_t& r0, uint32_t& r1, uint32_t& r2, uint32_t& r3,
                                        uint32_t addr) {
    asm volatile("ldmatrix.sync.aligned.m8n8.x4.shared.b16 {%0,%1,%2,%3}, [%4];"
                 : "=r"(r0), "=r"(r1), "=r"(r2), "=r"(r3) : "r"(addr));
}
__device__ __forceinline__ void mma16816(float* c, uint32_t a0, uint32_t a1, uint32_t a2,
                                         uint32_t a3, uint32_t b0, uint32_t b1) {
    asm volatile("mma.sync.aligned.m16n8k16.row.col.f32.f16.f16.f32 "
                 "{%0,%1,%2,%3}, {%4,%5,%6,%7}, {%8,%9}, {%0,%1,%2,%3};"
                 : "+f"(c[0]), "+f"(c[1]), "+f"(c[2]), "+f"(c[3])
                 : "r"(a0), "r"(a1), "r"(a2), "r"(a3), "r"(b0), "r"(b1));
}

__global__ void convert_kernel(const float* __restrict__ X) {
    int idx = (blockIdx.x * blockDim.x + threadIdx.x) * 4;
    float4 v = *(const float4*)&X[idx];
    __half2* o = (__half2*)&X16[idx];
    o[0] = __floats2half2_rn(v.x, v.y);
    o[1] = __floats2half2_rn(v.z, v.w);
}

__device__ __forceinline__ int tri_off(int r) { return r * TILES - (r * (r - 1)) / 2; }

__global__ __launch_bounds__(256, 2)
void sim_loss_mma(const float* __restrict__ margin,
                  const int* __restrict__ tgt,
                  float* __restrict__ out) {
    const int b = blockIdx.x;
    int by = (int)((129.0 - sqrt(16641.0 - 8.0 * (double)b)) * 0.5);
    while (tri_off(by + 1) <= b) ++by;
    while (tri_off(by) > b) --by;
    const int bx = by + (b - tri_off(by));
    const bool diag = (by == bx);

    extern __shared__ __half dsm[];
    __half* As = dsm;               // BM*STR halves (34816 B)
    __half* Bs = dsm + BM * STR;    // BN*STR halves

    __shared__ int   cs[BN];
    __shared__ float cm[BN];
    __shared__ int   rt[BM];
    __shared__ float rm[BM];
    __shared__ float red[8];
    __shared__ int   flag;

    const int tid  = threadIdx.x;
    const int lane = tid & 31;
    const int wid  = tid >> 5;
    const int wm   = wid & 1;
    const int wn   = wid >> 1;
    const int rowBase = by * BM;
    const int colBase = bx * BN;

    const uint32_t sA = smem_u32(As);
    const uint32_t sB = smem_u32(Bs);

    // ---- one-shot full-K prefetch: 2 tiles x 128 rows x 16 chunks = 4096 x 16B ----
#pragma unroll
    for (int p = 0; p < 16; p++) {
        int id   = tid + p * 256;
        int isB  = id >> 11;            // 0: A, 1: B
        int e    = id & 2047;
        int row  = e >> 4;
        int ch   = e & 15;
        const __half* src = &X16[(size_t)((isB ? colBase : rowBase) + row) * DD + ch * 8];
        uint32_t dst = (isB ? sB : sA) + (uint32_t)(row * STR + ch * 8) * 2;
        cp_async16(dst, src);
    }
    CP_COMMIT();

    float acc[4][4][4];
#pragma unroll
    for (int mi = 0; mi < 4; mi++)
#pragma unroll
        for (int ni = 0; ni < 4; ni++)
#pragma unroll
            for (int q = 0; q < 4; q++) acc[mi][ni][q] = 0.0f;

    if (tid < 128) {
        cs[tid] = tgt[colBase + tid];
        cm[tid] = margin[colBase + tid];
        rt[tid] = tgt[rowBase + tid];
        rm[tid] = margin[rowBase + tid];
    }

    CP_WAIT0();
    __syncthreads();      // the ONLY mainloop barrier

    const int lrow = lane & 15;
    const int lchk = lane >> 4;

    // ---- 8 straight-line k16 phases, no barriers ----
#pragma unroll
    for (int ks = 0; ks < 8; ks++) {
        uint32_t a[4][4];
#pragma unroll
        for (int mi = 0; mi < 4; mi++) {
            uint32_t addr = sA + (uint32_t)((wm * 64 + mi * 16 + lrow) * STR + ks * 16 + lchk * 8) * 2;
            ldsm_x4(a[mi][0], a[mi][1], a[mi][2], a[mi][3], addr);
        }
        uint32_t bfr[2][4];
#pragma unroll
        for (int nb = 0; nb < 2; nb++) {
            uint32_t addr = sB + (uint32_t)((wn * 32 + nb * 16 + lrow) * STR + ks * 16 + lchk * 8) * 2;
            ldsm_x4(bfr[nb][0], bfr[nb][1], bfr[nb][2], bfr[nb][3], addr);
        }
#pragma unroll
        for (int mi = 0; mi < 4; mi++)
#pragma unroll
            for (int ni = 0; ni < 4; ni++)
                mma16816(acc[mi][ni], a[mi][0], a[mi][1], a[mi][2], a[mi][3],
                         bfr[ni >> 1][ni & 1], bfr[ni >> 1][2 + (ni & 1)]);
    }

    // ---- branchless epilogue ----
    const int r0l = (lane >> 2);
    const int c0l = (lane & 3) * 2;
    float local = 0.0f;

#pragma unroll
    for (int mi = 0; mi < 4; mi++) {
        const int rA = wm * 64 + mi * 16 + r0l;
        const int rB = rA + 8;
        const int   trA = rt[rA], trB = rt[rB];
        const float mgA = rm[rA], mgB = rm[rB];
#pragma unroll
        for (int ni = 0; ni < 4; ni++) {
            const int c0 = wn * 32 + ni * 8 + c0l;
            const int   tc0 = cs[c0], tc1 = cs[c0 + 1];
            const float mc0 = cm[c0], mc1 = cm[c0 + 1];
            float s, pos, neg;
            if (diag) {
                s = acc[mi][ni][0];
                pos = fmaxf(1.0f - s, 0.0f);
                neg = (s > mgA) ? s : 0.0f;
                local += (trA == tc0) ? pos : neg;
                s = acc[mi][ni][1];
                pos = fmaxf(1.0f - s, 0.0f);
                neg = (s > mgA) ? s : 0.0f;
                local += (trA == tc1) ? pos : neg;
                s = acc[mi][ni][2];
                pos = fmaxf(1.0f - s, 0.0f);
                neg = (s > mgB) ? s : 0.0f;
                local += (trB == tc0) ? pos : neg;
                s = acc[mi][ni][3];
                pos = fmaxf(1.0f - s, 0.0f);
                neg = (s > mgB) ? s : 0.0f;
                local += (trB == tc1) ? pos : neg;
            } else {
                s = acc[mi][ni][0];
                pos = 2.0f * fmaxf(1.0f - s, 0.0f);
                neg = ((s > mgA) ? s : 0.0f) + ((s > mc0) ? s : 0.0f);
                local += (trA == tc0) ? pos : neg;
                s = acc[mi][ni][1];
                pos = 2.0f * fmaxf(1.0f - s, 0.0f);
                neg = ((s > mgA) ? s : 0.0f) + ((s > mc1) ? s : 0.0f);
                local += (trA == tc1) ? pos : neg;
                s = acc[mi][ni][2];
                pos = 2.0f * fmaxf(1.0f - s, 0.0f);
                neg = ((s > mgB) ? s : 0.0f) + ((s > mc0) ? s : 0.0f);
                local += (trB == tc0) ? pos : neg;
                s = acc[mi][ni][3];
                pos = 2.0f * fmaxf(1.0f - s, 0.0f);
                neg = ((s > mgB) ? s : 0.0f) + ((s > mc1) ? s : 0.0f);
                local += (trB == tc1) ? pos : neg;
            }
        }
    }

    // ---- block reduce ----
#pragma unroll
    for (int off = 16; off > 0; off >>= 1)
        local += __shfl_xor_sync(0xFFFFFFFFu, local, off);
    if (lane == 0) red[wid] = local;
    __syncthreads();

    if (tid == 0) {
        float s = 0.0f;
#pragma unroll
        for (int w = 0; w < 8; w++) s += red[w];
        g_partial[b] = s;
    }

    // ---- deterministic last-block final reduce ----
    __threadfence();
    __syncthreads();
    if (tid == 0) flag = (atomicAdd(&g_count, 1) == NACT - 1) ? 1 : 0;
    __syncthreads();
    if (flag) {
        float v = 0.0f;
#pragma unroll
        for (int p = 0; p < NPAD / 256; p++)
            v += g_partial[tid + p * 256];
#pragma unroll
        for (int off = 16; off > 0; off >>= 1)
            v += __shfl_xor_sync(0xFFFFFFFFu, v, off);
        if (lane == 0) red[wid] = v;
        __syncthreads();
        if (tid == 0) {
            float s = 0.0f;
#pragma unroll
            for (int w = 0; w < 8; w++) s += red[w];
            out[0] = s / (float)NN;
            g_count = 0;
        }
    }
}

#define DSMEM_BYTES ((BM + BN) * STR * 2)   // 69632 B

extern "C" void kernel_launch(void* const* d_in, const int* in_sizes, int n_in,
                              void* d_out, int out_size) {
    const float* X      = (const float*)d_in[0];
    const float* margin = (const float*)d_in[1];
    const int*   tgt    = (const int*)d_in[2];
    float*       out    = (float*)d_out;

    static bool attr_set = false;
    if (!attr_set) {
        cudaFuncSetAttribute(sim_loss_mma, cudaFuncAttributeMaxDynamicSharedMemorySize, DSMEM_BYTES);
        attr_set = true;
    }

    convert_kernel<<<NN * DD / 4 / 256, 256>>>(X);
    sim_loss_mma<<<NACT, 256, DSMEM_BYTES>>>(margin, tgt, out);
}

// round 11
// speedup vs baseline: 1.1098x; 1.0739x over previous
#include <cuda_runtime.h>
#include <cuda_fp16.h>
#include <cstdint>
#include <math.h>

#define NN 8192
#define DD 128
#define BM 128
#define BN 128
#define STR 128           // halves; 256 B row, chunk-XOR swizzle -> conflict-free + 16B aligned
#define TILES 64
#define NACT (TILES*(TILES+1)/2)   // 2080
#define NPAD 2304

__device__ __half X16[NN * DD];
__device__ float  g_partial[NPAD];
__device__ int    g_count;

__device__ __forceinline__ uint32_t smem_u32(const void* p) {
    uint32_t a;
    asm("{ .reg .u64 t; cvta.to.shared.u64 t, %1; cvt.u32.u64 %0, t; }" : "=r"(a) : "l"(p));
    return a;
}
__device__ __forceinline__ void cp_async16(uint32_t s, const void* g) {
    asm volatile("cp.async.cg.shared.global [%0], [%1], 16;" :: "r"(s), "l"(g) : "memory");
}
#define CP_COMMIT() asm volatile("cp.async.commit_group;" ::: "memory")
#define CP_WAIT0()  asm volatile("cp.async.wait_group 0;" ::: "memory")

__device__ __forceinline__ void ldsm_x4(uint32_t& r0, uint32_t& r1, uint32_t& r2, uint32_t& r3,
                                        uint32_t addr) {
    asm volatile("ldmatrix.sync.aligned.m8n8.x4.shared.b16 {%0,%1,%2,%3}, [%4];"
                 : "=r"(r0), "=r"(r1), "=r"(r2), "=r"(r3) : "r"(addr));
}
// fp16-accumulate MMA: D/C packed half2 x2
__device__ __forceinline__ void mma16816h(uint32_t& c0, uint32_t& c1,
                                          uint32_t a0, uint32_t a1, uint32_t a2, uint32_t a3,
                                          uint32_t b0, uint32_t b1) {
    asm volatile("mma.sync.aligned.m16n8k16.row.col.f16.f16.f16.f16 "
                 "{%0,%1}, {%2,%3,%4,%5}, {%6,%7}, {%0,%1};"
                 : "+r"(c0), "+r"(c1)
                 : "r"(a0), "r"(a1), "r"(a2), "r"(a3), "r"(b0), "r"(b1));
}

__global__ void convert_kernel(const float* __restrict__ X) {
    int idx = (blockIdx.x * blockDim.x + threadIdx.x) * 4;
    float4 v = *(const float4*)&X[idx];
    __half2* o = (__half2*)&X16[idx];
    o[0] = __floats2half2_rn(v.x, v.y);
    o[1] = __floats2half2_rn(v.z, v.w);
}

__device__ __forceinline__ int tri_off(int r) { return r * TILES - (r * (r - 1)) / 2; }

__global__ __launch_bounds__(256, 3)
void sim_loss_mma(const float* __restrict__ margin,
                  const int* __restrict__ tgt,
                  float* __restrict__ out) {
    const int b = blockIdx.x;
    int by = (int)((129.0 - sqrt(16641.0 - 8.0 * (double)b)) * 0.5);
    while (tri_off(by + 1) <= b) ++by;
    while (tri_off(by) > b) --by;
    const int bx = by + (b - tri_off(by));
    const bool diag = (by == bx);

    extern __shared__ __half dsm[];
    __half* As = dsm;               // BM*STR halves = 32 KB
    __half* Bs = dsm + BM * STR;

    __shared__ int    cs[BN];
    __shared__ __half cm_h[BN];
    __shared__ int    rt[BM];
    __shared__ __half rm_h[BM];
    __shared__ float  red[8];
    __shared__ int    flag;

    const int tid  = threadIdx.x;
    const int lane = tid & 31;
    const int wid  = tid >> 5;
    const int wm   = wid & 1;
    const int wn   = wid >> 1;
    const int rowBase = by * BM;
    const int colBase = bx * BN;

    const uint32_t sA = smem_u32(As);
    const uint32_t sB = smem_u32(Bs);

    // ---- one-shot full-K prefetch with chunk-XOR swizzle ----
#pragma unroll
    for (int p = 0; p < 16; p++) {
        int id   = tid + p * 256;
        int isB  = id >> 11;
        int e    = id & 2047;
        int row  = e >> 4;
        int ch   = e & 15;
        const __half* src = &X16[(size_t)((isB ? colBase : rowBase) + row) * DD + ch * 8];
        int swch = ch ^ (row & 7);
        uint32_t dst = (isB ? sB : sA) + (uint32_t)(row * STR + swch * 8) * 2;
        cp_async16(dst, src);
    }
    CP_COMMIT();

    uint32_t acc[4][4][2];
#pragma unroll
    for (int mi = 0; mi < 4; mi++)
#pragma unroll
        for (int ni = 0; ni < 4; ni++) { acc[mi][ni][0] = 0u; acc[mi][ni][1] = 0u; }

    if (tid < 128) {
        cs[tid]   = tgt[colBase + tid];
        cm_h[tid] = __float2half(margin[colBase + tid]);
        rt[tid]   = tgt[rowBase + tid];
        rm_h[tid] = __float2half(margin[rowBase + tid]);
    }

    CP_WAIT0();
    __syncthreads();

    const int lrow = lane & 15;
    const int lchk = lane >> 4;

    // ---- 8 straight-line k16 phases ----
#pragma unroll
    for (int ks = 0; ks < 8; ks++) {
        uint32_t a[4][4];
#pragma unroll
        for (int mi = 0; mi < 4; mi++) {
            int row = wm * 64 + mi * 16 + lrow;
            int swch = (ks * 2 + lchk) ^ (row & 7);
            uint32_t addr = sA + (uint32_t)(row * STR + swch * 8) * 2;
            ldsm_x4(a[mi][0], a[mi][1], a[mi][2], a[mi][3], addr);
        }
        uint32_t bfr[2][4];
#pragma unroll
        for (int nb = 0; nb < 2; nb++) {
            int row = wn * 32 + nb * 16 + lrow;
            int swch = (ks * 2 + lchk) ^ (row & 7);
            uint32_t addr = sB + (uint32_t)(row * STR + swch * 8) * 2;
            ldsm_x4(bfr[nb][0], bfr[nb][1], bfr[nb][2], bfr[nb][3], addr);
        }
#pragma unroll
        for (int mi = 0; mi < 4; mi++)
#pragma unroll
            for (int ni = 0; ni < 4; ni++)
                mma16816h(acc[mi][ni][0], acc[mi][ni][1],
                          a[mi][0], a[mi][1], a[mi][2], a[mi][3],
                          bfr[ni >> 1][ni & 1], bfr[ni >> 1][2 + (ni & 1)]);
    }

    // ---- half2 SIMD epilogue ----
    // d0 = (r, c),(r, c+1); d1 = (r+8, c),(r+8, c+1); r=lane/4, c=2*(lane&3)
    const int r0l = (lane >> 2);
    const int c0l = (lane & 3) * 2;
    const __half2 one2  = __float2half2_rn(1.0f);
    const __half2 zero2 = __float2half2_rn(0.0f);
    const __half2 two2  = __float2half2_rn(2.0f);
    float local = 0.0f;

#pragma unroll
    for (int mi = 0; mi < 4; mi++) {
        const int rA = wm * 64 + mi * 16 + r0l;
        const int rB = rA + 8;
        const int trA = rt[rA], trB = rt[rB];
        const __half2 mgA2 = __half2half2(rm_h[rA]);
        const __half2 mgB2 = __half2half2(rm_h[rB]);
#pragma unroll
        for (int ni = 0; ni < 4; ni++) {
            const int c0 = wn * 32 + ni * 8 + c0l;
            const int tc0 = cs[c0], tc1 = cs[c0 + 1];
            const __half2 mc2 = *(const __half2*)&cm_h[c0];
            uint32_t eqAu = ((trA == tc0) ? 0x3C00u : 0u) | ((trA == tc1) ? 0x3C000000u : 0u);
            uint32_t eqBu = ((trB == tc0) ? 0x3C00u : 0u) | ((trB == tc1) ? 0x3C000000u : 0u);
            const __half2 eqA2 = *reinterpret_cast<__half2*>(&eqAu);
            const __half2 eqB2 = *reinterpret_cast<__half2*>(&eqBu);
            const __half2 sA2 = *reinterpret_cast<__half2*>(&acc[mi][ni][0]);
            const __half2 sB2 = *reinterpret_cast<__half2*>(&acc[mi][ni][1]);

            __half2 neg, pos, ctr;
            float2 f;
            if (diag) {
                neg = __hmul2(sA2, __hgt2(sA2, mgA2));
                pos = __hmax2(__hsub2(one2, sA2), zero2);
                ctr = __hfma2(eqA2, __hsub2(pos, neg), neg);
                f = __half22float2(ctr);
                local += f.x + f.y;

                neg = __hmul2(sB2, __hgt2(sB2, mgB2));
                pos = __hmax2(__hsub2(one2, sB2), zero2);
                ctr = __hfma2(eqB2, __hsub2(pos, neg), neg);
                f = __half22float2(ctr);
                local += f.x + f.y;
            } else {
                neg = __hmul2(sA2, __hadd2(__hgt2(sA2, mgA2), __hgt2(sA2, mc2)));
                pos = __hmul2(two2, __hmax2(__hsub2(one2, sA2), zero2));
                ctr = __hfma2(eqA2, __hsub2(pos, neg), neg);
                f = __half22float2(ctr);
                local += f.x + f.y;

                neg = __hmul2(sB2, __hadd2(__hgt2(sB2, mgB2), __hgt2(sB2, mc2)));
                pos = __hmul2(two2, __hmax2(__hsub2(one2, sB2), zero2));
                ctr = __hfma2(eqB2, __hsub2(pos, neg), neg);
                f = __half22float2(ctr);
                local += f.x + f.y;
            }
        }
    }

    // ---- block reduce ----
#pragma unroll
    for (int off = 16; off > 0; off >>= 1)
        local += __shfl_xor_sync(0xFFFFFFFFu, local, off);
    if (lane == 0) red[wid] = local;
    __syncthreads();

    if (tid == 0) {
        float s = 0.0f;
#pragma unroll
        for (int w = 0; w < 8; w++) s += red[w];
        g_partial[b] = s;
    }

    // ---- deterministic last-block final reduce ----
    __threadfence();
    __syncthreads();
    if (tid == 0) flag = (atomicAdd(&g_count, 1) == NACT - 1) ? 1 : 0;
    __syncthreads();
    if (flag) {
        float v = 0.0f;
#pragma unroll
        for (int p = 0; p < NPAD / 256; p++)
            v += g_partial[tid + p * 256];
#pragma unroll
        for (int off = 16; off > 0; off >>= 1)
            v += __shfl_xor_sync(0xFFFFFFFFu, v, off);
        if (lane == 0) red[wid] = v;
        __syncthreads();
        if (tid == 0) {
            float s = 0.0f;
#pragma unroll
            for (int w = 0; w < 8; w++) s += red[w];
            out[0] = s / (float)NN;
            g_count = 0;
        }
    }
}

#define DSMEM_BYTES ((BM + BN) * STR * 2)   // 65536 B

extern "C" void kernel_launch(void* const* d_in, const int* in_sizes, int n_in,
                              void* d_out, int out_size) {
    const float* X      = (const float*)d_in[0];
    const float* margin = (const float*)d_in[1];
    const int*   tgt    = (const int*)d_in[2];
    float*       out    = (float*)d_out;

    static bool attr_set = false;
    if (!attr_set) {
        cudaFuncSetAttribute(sim_loss_mma, cudaFuncAttributeMaxDynamicSharedMemorySize, DSMEM_BYTES);
        attr_set = true;
    }

    convert_kernel<<<NN * DD / 4 / 256, 256>>>(X);
    sim_loss_mma<<<NACT, 256, DSMEM_BYTES>>>(margin, tgt, out);
}